// round 2
// baseline (speedup 1.0000x reference)
#include <cuda_runtime.h>
#include <math.h>

// ---------------------------------------------------------------------------
// ConvSlimCapsule3D: conv3d (votes) + 3-iteration dynamic routing + squash
// Shapes: x(2,8,16,32,32,32) w(128,16,3,3,3) b(128) biases(8,16,1,1,1)
// out: (2,8,16,32,32,32) = 8388608 floats
// Conv uses packed f32x2 FFMA2 (2 positions per thread share each weight).
// ---------------------------------------------------------------------------

typedef unsigned long long u64;

// Votes scratch: [b][pos][in*128 + oc] = 2 * 32768 * 1024 floats (256 MB)
__device__ float g_votes[67108864];

__device__ __forceinline__ void ffma2(u64 &d, u64 a, u64 b) {
    asm("fma.rn.f32x2 %0, %1, %2, %0;" : "+l"(d) : "l"(a), "l"(b));
}
__device__ __forceinline__ u64 pack2(float lo, float hi) {
    u64 r; asm("mov.b64 %0, {%1, %2};" : "=l"(r) : "f"(lo), "f"(hi)); return r;
}
__device__ __forceinline__ float2 unpack2(u64 v) {
    float lo, hi; asm("mov.b64 {%0, %1}, %2;" : "=f"(lo), "=f"(hi) : "l"(v));
    return make_float2(lo, hi);
}

// ---------------- Conv kernel -------------------------------------------
// Tile: 4(z) x 8(y) x 16(x) = 512 positions / block, 256 threads, each thread
// owns the position pair (x, x+8) packed into f32x2 lanes.
// SMEM: input pair tile [16][6][10][10] u64  = 9600 u64 (76.8 KB)
//       duplicated weight chunk [8*16][28] u64 = 3584 u64 (28.7 KB)
#define INS_U64   9600
#define WSD_U64   3584
#define CONV_SMEM ((INS_U64 + WSD_U64) * 8)

__global__ __launch_bounds__(256, 2)
void conv_votes_kernel(const float* __restrict__ x,
                       const float* __restrict__ w,
                       const float* __restrict__ cb) {
    extern __shared__ u64 sm64[];
    u64* ins2 = sm64;             // input pairs
    u64* wsd  = sm64 + INS_U64;   // duplicated weights, rows padded to 28

    const int n = blockIdx.y;          // sample = b*8 + i
    const int b = n >> 3;
    const int i = n & 7;
    const int tile = blockIdx.x;       // 64 tiles: 2(x) * 4(y) * 8(z)
    const int x0 = (tile & 1) * 16;
    const int y0 = ((tile >> 1) & 3) * 8;
    const int z0 = (tile >> 3) * 4;
    const int tid = threadIdx.x;

    // ---- fill input pair tile (halo, zero padded): pair = (xx, xx+8) ----
    const float* xn = x + (size_t)n * 524288;  // 16*32768
    for (int idx = tid; idx < INS_U64; idx += 256) {
        int ic = idx / 600;
        int r  = idx - ic * 600;
        int zz = r / 100;  r -= zz * 100;
        int yy = r / 10;
        int px = r - yy * 10;
        int gz = z0 + zz - 1, gy = y0 + yy - 1;
        int gx0 = x0 + px - 1, gx1 = gx0 + 8;
        float v0 = 0.0f, v1 = 0.0f;
        if ((unsigned)gz < 32u && (unsigned)gy < 32u) {
            const float* row = xn + ic * 32768 + gz * 1024 + gy * 32;
            if ((unsigned)gx0 < 32u) v0 = row[gx0];
            if ((unsigned)gx1 < 32u) v1 = row[gx1];
        }
        ((float2*)ins2)[idx] = make_float2(v0, v1);
    }

    const int lx = tid & 7;
    const int ly = (tid >> 3) & 7;
    const int lz = tid >> 6;
    const int ibase = (lz * 10 + ly) * 10 + lx;
    const int gpos = (z0 + lz) * 1024 + (y0 + ly) * 32 + (x0 + lx);
    float* vout = g_votes + (size_t)(b * 32768 + gpos) * 1024 + i * 128;
    // second position of the pair is +8 in x -> +8*1024 floats

    // ---- 16 chunks of 8 output channels ----
    for (int chunk = 0; chunk < 16; ++chunk) {
        const int c0 = chunk << 3;
        __syncthreads();  // previous chunk's weight reads done
        for (int idx = tid; idx < 3456; idx += 256) {
            int u = idx / 432;
            int r = idx - u * 432;
            int ic = r / 27;
            int t  = r - ic * 27;
            float v = w[(c0 + u) * 432 + r];
            ((float2*)wsd)[(u * 16 + ic) * 28 + t] = make_float2(v, v);
        }
        __syncthreads();

        u64 acc[8];
#pragma unroll
        for (int u = 0; u < 8; ++u) {
            float bv = __ldg(&cb[c0 + u]);
            acc[u] = pack2(bv, bv);
        }

#pragma unroll 1
        for (int ic = 0; ic < 16; ++ic) {
            u64 ab[27];
            const u64* ib = ins2 + ic * 600 + ibase;
#pragma unroll
            for (int dz = 0; dz < 3; ++dz)
#pragma unroll
                for (int dy = 0; dy < 3; ++dy)
#pragma unroll
                    for (int dx = 0; dx < 3; ++dx)
                        ab[(dz * 3 + dy) * 3 + dx] = ib[dz * 100 + dy * 10 + dx];
            const u64* wr = wsd + ic * 28;
#pragma unroll
            for (int u = 0; u < 8; ++u) {
                const u64* wu = wr + u * 448;  // u*16*28
#pragma unroll
                for (int t = 0; t < 27; ++t)
                    ffma2(acc[u], ab[t], wu[t]);
            }
        }

        // ---- direct vote stores: 8 consecutive channels per position ----
        float lo[8], hi[8];
#pragma unroll
        for (int u = 0; u < 8; ++u) {
            float2 f = unpack2(acc[u]);
            lo[u] = f.x; hi[u] = f.y;
        }
        *(float4*)(vout + c0)            = make_float4(lo[0], lo[1], lo[2], lo[3]);
        *(float4*)(vout + c0 + 4)        = make_float4(lo[4], lo[5], lo[6], lo[7]);
        *(float4*)(vout + 8192 + c0)     = make_float4(hi[0], hi[1], hi[2], hi[3]);
        *(float4*)(vout + 8192 + c0 + 4) = make_float4(hi[4], hi[5], hi[6], hi[7]);
    }
}

// ---------------- Routing kernel -----------------------------------------
// One warp per (b, pos). lane = o*4 + g; lane holds atoms [g*4, g*4+4) of
// out-capsule o across all 8 input capsules (32 vote floats in registers).
// Atom reductions: shfl xor {1,2}. Out-dim softmax reductions: shfl xor {4,8,16}.
// Softmax max-subtraction dropped: logits are sums of <=2 cosine distances,
// so |logit| <= 2 and exp is safe.
__global__ __launch_bounds__(256)
void routing_kernel(const float* __restrict__ biases,
                    float* __restrict__ out) {
    __shared__ float sf[8 * 132];  // float4[8 warps][33]

    const int tid  = threadIdx.x;
    const int wrp  = tid >> 5;
    const int lane = tid & 31;
    const int o = lane >> 2;
    const int g = lane & 3;
    const int blk = blockIdx.x;
    const int b = blk >> 12;                // 4096 blocks per batch
    const int posbase = (blk & 4095) << 3;  // 8 positions per block
    const int pos = posbase + wrp;

    const float4* vp =
        (const float4*)(g_votes + (size_t)(b * 32768 + pos) * 1024);

    float v[8][4];
    float vn[8];
#pragma unroll
    for (int in = 0; in < 8; ++in) {
        float4 t = vp[in * 32 + o * 4 + g];
        v[in][0] = t.x; v[in][1] = t.y; v[in][2] = t.z; v[in][3] = t.w;
        float s = t.x * t.x + t.y * t.y + t.z * t.z + t.w * t.w;
        s += __shfl_xor_sync(0xffffffffu, s, 1);
        s += __shfl_xor_sync(0xffffffffu, s, 2);
        vn[in] = sqrtf(s);
    }
    const float4 bs = ((const float4*)biases)[o * 4 + g];

    float logit[8];
#pragma unroll
    for (int in = 0; in < 8; ++in) logit[in] = 0.0f;

    float p0, p1, p2, p3;
    for (int it = 0; it < 3; ++it) {
        float route[8];
        if (it == 0) {
#pragma unroll
            for (int in = 0; in < 8; ++in) route[in] = 0.125f;
        } else {
#pragma unroll
            for (int in = 0; in < 8; ++in) {
                float e = __expf(logit[in]);
                float s = e;
                s += __shfl_xor_sync(0xffffffffu, s, 4);
                s += __shfl_xor_sync(0xffffffffu, s, 8);
                s += __shfl_xor_sync(0xffffffffu, s, 16);
                route[in] = e / s;
            }
        }
        p0 = bs.x; p1 = bs.y; p2 = bs.z; p3 = bs.w;
#pragma unroll
        for (int in = 0; in < 8; ++in) {
            p0 = fmaf(route[in], v[in][0], p0);
            p1 = fmaf(route[in], v[in][1], p1);
            p2 = fmaf(route[in], v[in][2], p2);
            p3 = fmaf(route[in], v[in][3], p3);
        }
        if (it < 2) {
            float pn = p0 * p0 + p1 * p1 + p2 * p2 + p3 * p3;
            pn += __shfl_xor_sync(0xffffffffu, pn, 1);
            pn += __shfl_xor_sync(0xffffffffu, pn, 2);
            pn = sqrtf(pn);
#pragma unroll
            for (int in = 0; in < 8; ++in) {
                float d = p0 * v[in][0] + p1 * v[in][1] +
                          p2 * v[in][2] + p3 * v[in][3];
                d += __shfl_xor_sync(0xffffffffu, d, 1);
                d += __shfl_xor_sync(0xffffffffu, d, 2);
                logit[in] += d / fmaxf(pn * vn[in], 1e-8f);
            }
        }
    }

    // squash over atoms
    float nsq = p0 * p0 + p1 * p1 + p2 * p2 + p3 * p3;
    nsq += __shfl_xor_sync(0xffffffffu, nsq, 1);
    nsq += __shfl_xor_sync(0xffffffffu, nsq, 2);
    const float nrm = sqrtf(nsq);
    const float scale = (nsq / (1.0f + nsq)) / (nrm + 1e-12f);

    ((float4*)sf)[wrp * 33 + (o * 4 + g)] =
        make_float4(p0 * scale, p1 * scale, p2 * scale, p3 * scale);
    __syncthreads();

    // out[(b*128 + oa)*32768 + pos], transposed write for coalescing
    for (int j = tid; j < 1024; j += 256) {
        const int oa = j >> 3;
        const int pp = j & 7;
        out[(size_t)(b * 128 + oa) * 32768 + posbase + pp] = sf[pp * 132 + oa];
    }
}

// ---------------- Launch ---------------------------------------------------
extern "C" void kernel_launch(void* const* d_in, const int* in_sizes, int n_in,
                              void* d_out, int out_size) {
    const float* x      = (const float*)d_in[0];
    const float* w      = (const float*)d_in[1];
    const float* cb     = (const float*)d_in[2];
    const float* biases = (const float*)d_in[3];
    float* out = (float*)d_out;

    cudaFuncSetAttribute(conv_votes_kernel,
                         cudaFuncAttributeMaxDynamicSharedMemorySize,
                         CONV_SMEM);
    conv_votes_kernel<<<dim3(64, 16), 256, CONV_SMEM>>>(x, w, cb);
    routing_kernel<<<8192, 256>>>(biases, out);
}

// round 4
// speedup vs baseline: 4.1939x; 4.1939x over previous
#include <cuda_runtime.h>
#include <cuda_bf16.h>
#include <math.h>

typedef unsigned int u32;
typedef unsigned long long u64;
typedef unsigned short u16;

// ---------------------------------------------------------------------------
// ConvSlimCapsule3D via warp-level bf16 MMA (mma.sync m16n8k16) + routing.
// x(2,8,16,32,32,32) w(128,16,3,3,3) cb(128) biases(8,16,1,1,1)
// votes[b][pos][i*128+oc] : 256 MB scratch
// ---------------------------------------------------------------------------

__device__ float g_votes[67108864];
// weights, bf16 split: [tap=27][split=2][ic=16][oc=128]
__device__ __align__(16) u16 g_wb[110592];

// ---- SMEM layout (bytes) ----
// halo hi: 400 rows * 48B ; halo lo: same ; B: 2 bufs * 2 splits * 16*272
#define OFF_HH 0
#define OFF_HL 19200
#define OFF_B  38400
#define B_BUF  8704
#define B_SPLIT 4352
#define B_ROW  272
#define CONV_SMEM (38400 + 2 * B_BUF)   // 55808

__device__ __forceinline__ u32 smem_u32(const void* p) {
    u32 a;
    asm("{ .reg .u64 t; cvta.to.shared.u64 t, %1; cvt.u32.u64 %0, t; }"
        : "=r"(a) : "l"(p));
    return a;
}

#define LDSM_X4(r, a)                                                        \
    asm volatile("ldmatrix.sync.aligned.m8n8.x4.shared.b16 "                 \
                 "{%0,%1,%2,%3}, [%4];"                                      \
                 : "=r"((r)[0]), "=r"((r)[1]), "=r"((r)[2]), "=r"((r)[3])    \
                 : "r"(a))
#define LDSM_X4T(r0, r1, r2, r3, a)                                          \
    asm volatile("ldmatrix.sync.aligned.m8n8.x4.trans.shared.b16 "           \
                 "{%0,%1,%2,%3}, [%4];"                                      \
                 : "=r"(r0), "=r"(r1), "=r"(r2), "=r"(r3) : "r"(a))
#define MMA_BF16(d, a, b)                                                    \
    asm volatile("mma.sync.aligned.m16n8k16.row.col.f32.bf16.bf16.f32 "     \
                 "{%0,%1,%2,%3}, {%4,%5,%6,%7}, {%8,%9}, {%0,%1,%2,%3};"    \
                 : "+f"((d)[0]), "+f"((d)[1]), "+f"((d)[2]), "+f"((d)[3])    \
                 : "r"((a)[0]), "r"((a)[1]), "r"((a)[2]), "r"((a)[3]),       \
                   "r"((b)[0]), "r"((b)[1]))

// ---------------- weight prep ----------------------------------------------
__global__ void build_wb_kernel(const float* __restrict__ w) {
    int idx = blockIdx.x * 256 + threadIdx.x;  // 110592 total
    if (idx >= 110592) return;
    int tap = idx >> 12;
    int r = idx & 4095;
    int split = r >> 11;
    int ic = (r >> 7) & 15;
    int oc = r & 127;
    float v = w[oc * 432 + ic * 27 + tap];
    __nv_bfloat16 h = __float2bfloat16(v);
    if (split == 0) {
        g_wb[idx] = __bfloat16_as_ushort(h);
    } else {
        __nv_bfloat16 l = __float2bfloat16(v - __bfloat162float(h));
        g_wb[idx] = __bfloat16_as_ushort(l);
    }
}

// ---------------- conv via warp MMA -----------------------------------------
// CTA: 128 positions (2z x 8y x 8x) x 128 oc. 8 warps: 4 along M (32 pos),
// 2 along N (64 oc). K = 27 taps x 16 ic; one k16 MMA step per tap.
// 3 split-products per tap: Ah*Bh + Ah*Bl + Al*Bh.
__global__ __launch_bounds__(256)
void conv_mma_kernel(const float* __restrict__ x, const float* __restrict__ cb) {
    extern __shared__ char sm[];
    const u32 smb = smem_u32(sm);
    const int tid = threadIdx.x;
    const int wid = tid >> 5, lane = tid & 31;
    const int n = blockIdx.y, b = n >> 3, i = n & 7;
    const int tile = blockIdx.x;                 // 256 tiles: 4x*4y*16z
    const int x0 = (tile & 3) * 8;
    const int y0 = ((tile >> 2) & 3) * 8;
    const int z0 = (tile >> 4) * 2;

    // ---- halo tile: [hz4][hy10][hx10][ic16] bf16, row stride 48B, split ----
    const float* xn = x + (size_t)n * 524288;
    for (int idx = tid; idx < 6400; idx += 256) {
        int ic = idx / 400, h = idx - ic * 400;
        int hz = h / 100, rp = h - hz * 100;
        int hy = rp / 10, hx = rp - hy * 10;
        int gz = z0 + hz - 1, gy = y0 + hy - 1, gx = x0 + hx - 1;
        float v = 0.0f;
        if ((unsigned)gz < 32u && (unsigned)gy < 32u && (unsigned)gx < 32u)
            v = xn[ic * 32768 + gz * 1024 + gy * 32 + gx];
        __nv_bfloat16 hb = __float2bfloat16(v);
        __nv_bfloat16 lb = __float2bfloat16(v - __bfloat162float(hb));
        int so = h * 48 + ic * 2;
        *(u16*)(sm + OFF_HH + so) = __bfloat16_as_ushort(hb);
        *(u16*)(sm + OFF_HL + so) = __bfloat16_as_ushort(lb);
    }

    // ---- per-lane ldmatrix base addresses ----
    const int wm = (wid >> 1) * 32;
    const int wn = (wid & 1) * 64;
    const int lr = lane & 15;
    const int ksel = (lane >> 4) * 16;   // +16B for k8-15 tiles
    u32 laddrA[2];
    {
#pragma unroll
        for (int f = 0; f < 2; ++f) {
            int pos = wm + f * 16 + lr;
            int lz = pos >> 6, ly = (pos >> 3) & 7, lx = pos & 7;
            laddrA[f] = smb + OFF_HH + (lz * 100 + ly * 10 + lx) * 48 + ksel;
        }
    }
    u32 baddr[4];
#pragma unroll
    for (int p = 0; p < 4; ++p) {
        int k = lane & 15;
        int nc = wn + p * 16 + ((lane >> 4) & 1) * 8;
        baddr[p] = smb + OFF_B + k * B_ROW + nc * 2;
    }

    float acc[2][8][4];
#pragma unroll
    for (int f = 0; f < 2; ++f)
#pragma unroll
        for (int nf = 0; nf < 8; ++nf)
#pragma unroll
            for (int q = 0; q < 4; ++q) acc[f][nf][q] = 0.0f;

    // ---- stage B tap 0 ----
    {
        const char* gsrc = (const char*)g_wb;  // tap 0
#pragma unroll
        for (int c = tid; c < 512; c += 256) {
            int split = c >> 8, r = (c >> 4) & 15, seg = c & 15;
            u32 d = smb + OFF_B + split * B_SPLIT + r * B_ROW + seg * 16;
            const char* s = gsrc + split * 4096 + r * 256 + seg * 16;
            asm volatile("cp.async.ca.shared.global [%0], [%1], 16;"
                         :: "r"(d), "l"(s));
        }
        asm volatile("cp.async.commit_group;" ::: "memory");
    }

#pragma unroll 1
    for (int tap = 0; tap < 27; ++tap) {
        if (tap + 1 < 27) {
            const char* gsrc = (const char*)g_wb + (tap + 1) * 8192;
            u32 dbase = smb + OFF_B + ((tap + 1) & 1) * B_BUF;
#pragma unroll
            for (int c = tid; c < 512; c += 256) {
                int split = c >> 8, r = (c >> 4) & 15, seg = c & 15;
                u32 d = dbase + split * B_SPLIT + r * B_ROW + seg * 16;
                const char* s = gsrc + split * 4096 + r * 256 + seg * 16;
                asm volatile("cp.async.ca.shared.global [%0], [%1], 16;"
                             :: "r"(d), "l"(s));
            }
            asm volatile("cp.async.commit_group;" ::: "memory");
            asm volatile("cp.async.wait_group 1;" ::: "memory");
        } else {
            asm volatile("cp.async.wait_group 0;" ::: "memory");
        }
        __syncthreads();  // buf[tap&1] ready; halo visible on tap 0

        const int dz = tap / 9;
        const int rm = tap - dz * 9;
        const int dy = rm / 3, dx = rm - dy * 3;
        const u32 delta = (u32)((dz * 100 + dy * 10 + dx) * 48);

        u32 ah[2][4], al[2][4];
#pragma unroll
        for (int f = 0; f < 2; ++f) {
            LDSM_X4(ah[f], laddrA[f] + delta);
            LDSM_X4(al[f], laddrA[f] + delta + 19200u);
        }
        const u32 bufo = (u32)((tap & 1) * B_BUF);
        u32 bh[8][2], bl[8][2];
#pragma unroll
        for (int p = 0; p < 4; ++p) {
            u32 r0, r1, r2, r3;
            LDSM_X4T(r0, r1, r2, r3, baddr[p] + bufo);
            bh[p * 2][0] = r0; bh[p * 2][1] = r1;
            bh[p * 2 + 1][0] = r2; bh[p * 2 + 1][1] = r3;
            LDSM_X4T(r0, r1, r2, r3, baddr[p] + bufo + B_SPLIT);
            bl[p * 2][0] = r0; bl[p * 2][1] = r1;
            bl[p * 2 + 1][0] = r2; bl[p * 2 + 1][1] = r3;
        }

#pragma unroll
        for (int f = 0; f < 2; ++f)
#pragma unroll
            for (int nf = 0; nf < 8; ++nf) {
                MMA_BF16(acc[f][nf], ah[f], bh[nf]);
                MMA_BF16(acc[f][nf], ah[f], bl[nf]);
                MMA_BF16(acc[f][nf], al[f], bh[nf]);
            }
        __syncthreads();  // compute done before buf reuse
    }

    // ---- epilogue: add conv bias, store votes ----
    float2 cbv[8];
#pragma unroll
    for (int nf = 0; nf < 8; ++nf)
        cbv[nf] = *(const float2*)(cb + wn + nf * 8 + (lane & 3) * 2);

#pragma unroll
    for (int f = 0; f < 2; ++f) {
        int pos0 = wm + f * 16 + (lane >> 2);
#pragma unroll
        for (int half = 0; half < 2; ++half) {
            int pos = pos0 + half * 8;
            int lz = pos >> 6, ly = (pos >> 3) & 7, lx = pos & 7;
            int gpos = (z0 + lz) * 1024 + (y0 + ly) * 32 + (x0 + lx);
            float* vrow =
                g_votes + (size_t)(b * 32768 + gpos) * 1024 + i * 128;
#pragma unroll
            for (int nf = 0; nf < 8; ++nf) {
                int col = wn + nf * 8 + (lane & 3) * 2;
                float2 o;
                o.x = acc[f][nf][half * 2 + 0] + cbv[nf].x;
                o.y = acc[f][nf][half * 2 + 1] + cbv[nf].y;
                *(float2*)(vrow + col) = o;
            }
        }
    }
}

// ---------------- Routing kernel (unchanged) --------------------------------
__global__ __launch_bounds__(256)
void routing_kernel(const float* __restrict__ biases,
                    float* __restrict__ out) {
    __shared__ float sf[8 * 132];

    const int tid  = threadIdx.x;
    const int wrp  = tid >> 5;
    const int lane = tid & 31;
    const int o = lane >> 2;
    const int g = lane & 3;
    const int blk = blockIdx.x;
    const int b = blk >> 12;
    const int posbase = (blk & 4095) << 3;
    const int pos = posbase + wrp;

    const float4* vp =
        (const float4*)(g_votes + (size_t)(b * 32768 + pos) * 1024);

    float v[8][4];
    float vn[8];
#pragma unroll
    for (int in = 0; in < 8; ++in) {
        float4 t = vp[in * 32 + o * 4 + g];
        v[in][0] = t.x; v[in][1] = t.y; v[in][2] = t.z; v[in][3] = t.w;
        float s = t.x * t.x + t.y * t.y + t.z * t.z + t.w * t.w;
        s += __shfl_xor_sync(0xffffffffu, s, 1);
        s += __shfl_xor_sync(0xffffffffu, s, 2);
        vn[in] = sqrtf(s);
    }
    const float4 bs = ((const float4*)biases)[o * 4 + g];

    float logit[8];
#pragma unroll
    for (int in = 0; in < 8; ++in) logit[in] = 0.0f;

    float p0, p1, p2, p3;
    for (int it = 0; it < 3; ++it) {
        float route[8];
        if (it == 0) {
#pragma unroll
            for (int in = 0; in < 8; ++in) route[in] = 0.125f;
        } else {
#pragma unroll
            for (int in = 0; in < 8; ++in) {
                float e = __expf(logit[in]);
                float s = e;
                s += __shfl_xor_sync(0xffffffffu, s, 4);
                s += __shfl_xor_sync(0xffffffffu, s, 8);
                s += __shfl_xor_sync(0xffffffffu, s, 16);
                route[in] = e / s;
            }
        }
        p0 = bs.x; p1 = bs.y; p2 = bs.z; p3 = bs.w;
#pragma unroll
        for (int in = 0; in < 8; ++in) {
            p0 = fmaf(route[in], v[in][0], p0);
            p1 = fmaf(route[in], v[in][1], p1);
            p2 = fmaf(route[in], v[in][2], p2);
            p3 = fmaf(route[in], v[in][3], p3);
        }
        if (it < 2) {
            float pn = p0 * p0 + p1 * p1 + p2 * p2 + p3 * p3;
            pn += __shfl_xor_sync(0xffffffffu, pn, 1);
            pn += __shfl_xor_sync(0xffffffffu, pn, 2);
            pn = sqrtf(pn);
#pragma unroll
            for (int in = 0; in < 8; ++in) {
                float d = p0 * v[in][0] + p1 * v[in][1] +
                          p2 * v[in][2] + p3 * v[in][3];
                d += __shfl_xor_sync(0xffffffffu, d, 1);
                d += __shfl_xor_sync(0xffffffffu, d, 2);
                logit[in] += d / fmaxf(pn * vn[in], 1e-8f);
            }
        }
    }

    float nsq = p0 * p0 + p1 * p1 + p2 * p2 + p3 * p3;
    nsq += __shfl_xor_sync(0xffffffffu, nsq, 1);
    nsq += __shfl_xor_sync(0xffffffffu, nsq, 2);
    const float nrm = sqrtf(nsq);
    const float scale = (nsq / (1.0f + nsq)) / (nrm + 1e-12f);

    ((float4*)sf)[wrp * 33 + (o * 4 + g)] =
        make_float4(p0 * scale, p1 * scale, p2 * scale, p3 * scale);
    __syncthreads();

    for (int j = tid; j < 1024; j += 256) {
        const int oa = j >> 3;
        const int pp = j & 7;
        out[(size_t)(b * 128 + oa) * 32768 + posbase + pp] = sf[pp * 132 + oa];
    }
}

// ---------------- Launch -----------------------------------------------------
extern "C" void kernel_launch(void* const* d_in, const int* in_sizes, int n_in,
                              void* d_out, int out_size) {
    const float* x      = (const float*)d_in[0];
    const float* w      = (const float*)d_in[1];
    const float* cb     = (const float*)d_in[2];
    const float* biases = (const float*)d_in[3];
    float* out = (float*)d_out;

    build_wb_kernel<<<432, 256>>>(w);

    cudaFuncSetAttribute(conv_mma_kernel,
                         cudaFuncAttributeMaxDynamicSharedMemorySize,
                         CONV_SMEM);
    conv_mma_kernel<<<dim3(256, 16), 256, CONV_SMEM>>>(x, cb);
    routing_kernel<<<8192, 256>>>(biases, out);
}

// round 6
// speedup vs baseline: 5.1853x; 1.2364x over previous
#include <cuda_runtime.h>
#include <cuda_fp16.h>
#include <math.h>

typedef unsigned int u32;
typedef unsigned short u16;

// ---------------------------------------------------------------------------
// ConvSlimCapsule3D via warp-level fp16 MMA (2-term split) + routing.
// x(2,8,16,32,32,32) w(128,16,3,3,3) cb(128) biases(8,16,1,1,1)
// ---------------------------------------------------------------------------

__device__ float g_votes[67108864];          // [b][pos][i*128+oc]
// weights fp16: [tap=27][half=2][ic=16][oc=64]
__device__ __align__(16) __half g_wb2[55296];

// ---- SMEM layout (bytes) ----
// halo hi/lo: 400 rows * 48B each ; B: 8 warps * 2 bufs * (16 rows * 144B)
#define OFF_HH 0
#define OFF_HL 19200
#define OFF_B  38400
#define B_ROW  144           // 16B-aligned rows; 144%128=16 -> conflict-free
#define B_BUF  (16 * B_ROW)  // 2304
#define CONV_SMEM (38400 + 8 * 2 * B_BUF)   // 75264

__device__ __forceinline__ u32 smem_u32(const void* p) {
    u32 a;
    asm("{ .reg .u64 t; cvta.to.shared.u64 t, %1; cvt.u32.u64 %0, t; }"
        : "=r"(a) : "l"(p));
    return a;
}

#define LDSM_X4(r, a)                                                        \
    asm volatile("ldmatrix.sync.aligned.m8n8.x4.shared.b16 "                 \
                 "{%0,%1,%2,%3}, [%4];"                                      \
                 : "=r"((r)[0]), "=r"((r)[1]), "=r"((r)[2]), "=r"((r)[3])    \
                 : "r"(a))
#define LDSM_X4T(r0, r1, r2, r3, a)                                          \
    asm volatile("ldmatrix.sync.aligned.m8n8.x4.trans.shared.b16 "           \
                 "{%0,%1,%2,%3}, [%4];"                                      \
                 : "=r"(r0), "=r"(r1), "=r"(r2), "=r"(r3) : "r"(a))
#define MMA_FP16(d, a, b)                                                    \
    asm volatile("mma.sync.aligned.m16n8k16.row.col.f32.f16.f16.f32 "       \
                 "{%0,%1,%2,%3}, {%4,%5,%6,%7}, {%8,%9}, {%0,%1,%2,%3};"    \
                 : "+f"((d)[0]), "+f"((d)[1]), "+f"((d)[2]), "+f"((d)[3])    \
                 : "r"((a)[0]), "r"((a)[1]), "r"((a)[2]), "r"((a)[3]),       \
                   "r"((b)[0]), "r"((b)[1]))

// ---------------- weight prep ----------------------------------------------
__global__ void build_wb_kernel(const float* __restrict__ w) {
    int idx = blockIdx.x * 256 + threadIdx.x;   // 55296 total
    if (idx >= 55296) return;
    int tap = idx >> 11;
    int r = idx & 2047;
    int half = r >> 10;
    int ic = (r >> 6) & 15;
    int oc = (half << 6) | (r & 63);
    g_wb2[idx] = __float2half_rn(w[oc * 432 + ic * 27 + tap]);
}

// ---------------- conv via warp MMA -----------------------------------------
// CTA: 128 positions (2z x 8y x 8x) x 128 oc. 8 warps: Wm=4 x Wn=2.
// A split fp16 (ah + al); B single fp16. 2 MMAs per (f,nf) per tap.
// Per-warp private B staging via cp.async + syncwarp (no CTA barriers in loop).
__global__ __launch_bounds__(256, 2)
void conv_mma_kernel(const float* __restrict__ x, const float* __restrict__ cb) {
    extern __shared__ char sm[];
    const u32 smb = smem_u32(sm);
    const int tid = threadIdx.x;
    const int wid = tid >> 5, lane = tid & 31;
    const int n = blockIdx.y, b = n >> 3, i = n & 7;
    const int tile = blockIdx.x;                 // 256 tiles: 4x*4y*16z
    const int x0 = (tile & 3) * 8;
    const int y0 = ((tile >> 2) & 3) * 8;
    const int z0 = (tile >> 4) * 2;

    const int wm = (wid >> 1) * 32;
    const int half = wid & 1;                    // oc half
    const int wn = half * 64;
    const u32 wbase = smb + OFF_B + (u32)wid * (2 * B_BUF);

    // ---- per-warp B staging: 4 x 16B per lane per tap ----
    const int srow0 = lane >> 3, sseg = lane & 7;   // rows lane/8 + {0,4,8,12}
    auto stage_tap = [&](int tap, int buf) {
        const __half* gsrc = g_wb2 + ((tap * 2 + half) << 10);
#pragma unroll
        for (int j = 0; j < 4; ++j) {
            int row = srow0 + j * 4;
            u32 d = wbase + (u32)buf * B_BUF + row * B_ROW + sseg * 16;
            const __half* s = gsrc + row * 64 + sseg * 8;
            asm volatile("cp.async.cg.shared.global [%0], [%1], 16;"
                         :: "r"(d), "l"(s));
        }
        asm volatile("cp.async.commit_group;" ::: "memory");
    };

    stage_tap(0, 0);

    // ---- halo tile: [400 rows][ic16] fp16 split, row stride 48B ----
    const float* xn = x + (size_t)n * 524288;
    for (int idx = tid; idx < 6400; idx += 256) {
        int ic = idx / 400, h = idx - ic * 400;
        int hz = h / 100, rp = h - hz * 100;
        int hy = rp / 10, hx = rp - hy * 10;
        int gz = z0 + hz - 1, gy = y0 + hy - 1, gx = x0 + hx - 1;
        float v = 0.0f;
        if ((unsigned)gz < 32u && (unsigned)gy < 32u && (unsigned)gx < 32u)
            v = xn[ic * 32768 + gz * 1024 + gy * 32 + gx];
        __half hh = __float2half_rn(v);
        __half hl = __float2half_rn(v - __half2float(hh));
        int so = h * 48 + ic * 2;
        *(u16*)(sm + OFF_HH + so) = __half_as_ushort(hh);
        *(u16*)(sm + OFF_HL + so) = __half_as_ushort(hl);
    }
    __syncthreads();   // the only CTA barrier before the epilogue

    // ---- per-lane ldmatrix addresses ----
    const int lr = lane & 15;
    const int ksel = (lane >> 4) * 16;
    u32 laddrA[2];
#pragma unroll
    for (int f = 0; f < 2; ++f) {
        int pos = wm + f * 16 + lr;
        int lz = pos >> 6, ly = (pos >> 3) & 7, lx = pos & 7;
        laddrA[f] = smb + OFF_HH + (lz * 100 + ly * 10 + lx) * 48 + ksel;
    }
    u32 baddr[4];
#pragma unroll
    for (int p = 0; p < 4; ++p) {
        int ncloc = p * 16 + ((lane >> 4) & 1) * 8;
        baddr[p] = wbase + (lane & 15) * B_ROW + ncloc * 2;
    }

    float acc[2][8][4];
#pragma unroll
    for (int f = 0; f < 2; ++f)
#pragma unroll
        for (int nf = 0; nf < 8; ++nf)
#pragma unroll
            for (int q = 0; q < 4; ++q) acc[f][nf][q] = 0.0f;

#pragma unroll 1
    for (int tap = 0; tap < 27; ++tap) {
        if (tap + 1 < 27) {
            stage_tap(tap + 1, (tap + 1) & 1);
            asm volatile("cp.async.wait_group 1;" ::: "memory");
        } else {
            asm volatile("cp.async.wait_group 0;" ::: "memory");
        }
        __syncwarp();

        const int dz = tap / 9;
        const int rm = tap - dz * 9;
        const int dy = rm / 3, dx = rm - dy * 3;
        const u32 delta = (u32)((dz * 100 + dy * 10 + dx) * 48);

        u32 ah[2][4], al[2][4];
#pragma unroll
        for (int f = 0; f < 2; ++f) {
            LDSM_X4(ah[f], laddrA[f] + delta);
            LDSM_X4(al[f], laddrA[f] + delta + 19200u);
        }
        const u32 bufo = (u32)((tap & 1) * B_BUF);
        u32 bh[8][2];
#pragma unroll
        for (int p = 0; p < 4; ++p) {
            u32 r0, r1, r2, r3;
            LDSM_X4T(r0, r1, r2, r3, baddr[p] + bufo);
            bh[p * 2][0] = r0; bh[p * 2][1] = r1;
            bh[p * 2 + 1][0] = r2; bh[p * 2 + 1][1] = r3;
        }

#pragma unroll
        for (int f = 0; f < 2; ++f)
#pragma unroll
            for (int nf = 0; nf < 8; ++nf) {
                MMA_FP16(acc[f][nf], ah[f], bh[nf]);
                MMA_FP16(acc[f][nf], al[f], bh[nf]);
            }
    }

    // ---- epilogue: add conv bias, store votes ----
    float2 cbv[8];
#pragma unroll
    for (int nf = 0; nf < 8; ++nf)
        cbv[nf] = *(const float2*)(cb + wn + nf * 8 + (lane & 3) * 2);

#pragma unroll
    for (int f = 0; f < 2; ++f) {
        int pos0 = wm + f * 16 + (lane >> 2);
#pragma unroll
        for (int hrow = 0; hrow < 2; ++hrow) {
            int pos = pos0 + hrow * 8;
            int lz = pos >> 6, ly = (pos >> 3) & 7, lx = pos & 7;
            int gpos = (z0 + lz) * 1024 + (y0 + ly) * 32 + (x0 + lx);
            float* vrow =
                g_votes + (size_t)(b * 32768 + gpos) * 1024 + i * 128;
#pragma unroll
            for (int nf = 0; nf < 8; ++nf) {
                int col = wn + nf * 8 + (lane & 3) * 2;
                float2 o;
                o.x = acc[f][nf][hrow * 2 + 0] + cbv[nf].x;
                o.y = acc[f][nf][hrow * 2 + 1] + cbv[nf].y;
                *(float2*)(vrow + col) = o;
            }
        }
    }
}

// ---------------- Routing kernel (unchanged) --------------------------------
__global__ __launch_bounds__(256)
void routing_kernel(const float* __restrict__ biases,
                    float* __restrict__ out) {
    __shared__ float sf[8 * 132];

    const int tid  = threadIdx.x;
    const int wrp  = tid >> 5;
    const int lane = tid & 31;
    const int o = lane >> 2;
    const int g = lane & 3;
    const int blk = blockIdx.x;
    const int b = blk >> 12;
    const int posbase = (blk & 4095) << 3;
    const int pos = posbase + wrp;

    const float4* vp =
        (const float4*)(g_votes + (size_t)(b * 32768 + pos) * 1024);

    float v[8][4];
    float vn[8];
#pragma unroll
    for (int in = 0; in < 8; ++in) {
        float4 t = vp[in * 32 + o * 4 + g];
        v[in][0] = t.x; v[in][1] = t.y; v[in][2] = t.z; v[in][3] = t.w;
        float s = t.x * t.x + t.y * t.y + t.z * t.z + t.w * t.w;
        s += __shfl_xor_sync(0xffffffffu, s, 1);
        s += __shfl_xor_sync(0xffffffffu, s, 2);
        vn[in] = sqrtf(s);
    }
    const float4 bs = ((const float4*)biases)[o * 4 + g];

    float logit[8];
#pragma unroll
    for (int in = 0; in < 8; ++in) logit[in] = 0.0f;

    float p0, p1, p2, p3;
    for (int it = 0; it < 3; ++it) {
        float route[8];
        if (it == 0) {
#pragma unroll
            for (int in = 0; in < 8; ++in) route[in] = 0.125f;
        } else {
#pragma unroll
            for (int in = 0; in < 8; ++in) {
                float e = __expf(logit[in]);
                float s = e;
                s += __shfl_xor_sync(0xffffffffu, s, 4);
                s += __shfl_xor_sync(0xffffffffu, s, 8);
                s += __shfl_xor_sync(0xffffffffu, s, 16);
                route[in] = e / s;
            }
        }
        p0 = bs.x; p1 = bs.y; p2 = bs.z; p3 = bs.w;
#pragma unroll
        for (int in = 0; in < 8; ++in) {
            p0 = fmaf(route[in], v[in][0], p0);
            p1 = fmaf(route[in], v[in][1], p1);
            p2 = fmaf(route[in], v[in][2], p2);
            p3 = fmaf(route[in], v[in][3], p3);
        }
        if (it < 2) {
            float pn = p0 * p0 + p1 * p1 + p2 * p2 + p3 * p3;
            pn += __shfl_xor_sync(0xffffffffu, pn, 1);
            pn += __shfl_xor_sync(0xffffffffu, pn, 2);
            pn = sqrtf(pn);
#pragma unroll
            for (int in = 0; in < 8; ++in) {
                float d = p0 * v[in][0] + p1 * v[in][1] +
                          p2 * v[in][2] + p3 * v[in][3];
                d += __shfl_xor_sync(0xffffffffu, d, 1);
                d += __shfl_xor_sync(0xffffffffu, d, 2);
                logit[in] += d / fmaxf(pn * vn[in], 1e-8f);
            }
        }
    }

    float nsq = p0 * p0 + p1 * p1 + p2 * p2 + p3 * p3;
    nsq += __shfl_xor_sync(0xffffffffu, nsq, 1);
    nsq += __shfl_xor_sync(0xffffffffu, nsq, 2);
    const float nrm = sqrtf(nsq);
    const float scale = (nsq / (1.0f + nsq)) / (nrm + 1e-12f);

    ((float4*)sf)[wrp * 33 + (o * 4 + g)] =
        make_float4(p0 * scale, p1 * scale, p2 * scale, p3 * scale);
    __syncthreads();

    for (int j = tid; j < 1024; j += 256) {
        const int oa = j >> 3;
        const int pp = j & 7;
        out[(size_t)(b * 128 + oa) * 32768 + posbase + pp] = sf[pp * 132 + oa];
    }
}

// ---------------- Launch -----------------------------------------------------
extern "C" void kernel_launch(void* const* d_in, const int* in_sizes, int n_in,
                              void* d_out, int out_size) {
    const float* x      = (const float*)d_in[0];
    const float* w      = (const float*)d_in[1];
    const float* cb     = (const float*)d_in[2];
    const float* biases = (const float*)d_in[3];
    float* out = (float*)d_out;

    build_wb_kernel<<<216, 256>>>(w);

    cudaFuncSetAttribute(conv_mma_kernel,
                         cudaFuncAttributeMaxDynamicSharedMemorySize,
                         CONV_SMEM);
    conv_mma_kernel<<<dim3(256, 16), 256, CONV_SMEM>>>(x, cb);
    routing_kernel<<<8192, 256>>>(biases, out);
}

// round 7
// speedup vs baseline: 6.5612x; 1.2653x over previous
#include <cuda_runtime.h>
#include <cuda_fp16.h>
#include <math.h>

typedef unsigned int u32;
typedef unsigned short u16;

// ---------------------------------------------------------------------------
// ConvSlimCapsule3D via warp-level fp16 MMA (2-term split, mixed-rate acc)
// + fast-math routing.
// x(2,8,16,32,32,32) w(128,16,3,3,3) cb(128) biases(8,16,1,1,1)
// ---------------------------------------------------------------------------

__device__ float g_votes[67108864];          // [b][pos][i*128+oc]
// weights fp16: [tap=27][half=2][ic=16][oc=64]
__device__ __align__(16) __half g_wb2[55296];

// ---- SMEM layout (bytes) ----
#define OFF_HH 0
#define OFF_HL 19200
#define OFF_B  38400
#define B_ROW  144           // 16B-aligned rows; 144%128=16 -> conflict-free
#define B_BUF  (16 * B_ROW)  // 2304
#define CONV_SMEM (38400 + 8 * 2 * B_BUF)   // 75264

__device__ __forceinline__ u32 smem_u32(const void* p) {
    u32 a;
    asm("{ .reg .u64 t; cvta.to.shared.u64 t, %1; cvt.u32.u64 %0, t; }"
        : "=r"(a) : "l"(p));
    return a;
}

#define LDSM_X4(r, a)                                                        \
    asm volatile("ldmatrix.sync.aligned.m8n8.x4.shared.b16 "                 \
                 "{%0,%1,%2,%3}, [%4];"                                      \
                 : "=r"((r)[0]), "=r"((r)[1]), "=r"((r)[2]), "=r"((r)[3])    \
                 : "r"(a))
#define LDSM_X4T(r0, r1, r2, r3, a)                                          \
    asm volatile("ldmatrix.sync.aligned.m8n8.x4.trans.shared.b16 "           \
                 "{%0,%1,%2,%3}, [%4];"                                      \
                 : "=r"(r0), "=r"(r1), "=r"(r2), "=r"(r3) : "r"(a))
#define MMA_F32(d, a, b)                                                     \
    asm volatile("mma.sync.aligned.m16n8k16.row.col.f32.f16.f16.f32 "       \
                 "{%0,%1,%2,%3}, {%4,%5,%6,%7}, {%8,%9}, {%0,%1,%2,%3};"    \
                 : "+f"((d)[0]), "+f"((d)[1]), "+f"((d)[2]), "+f"((d)[3])    \
                 : "r"((a)[0]), "r"((a)[1]), "r"((a)[2]), "r"((a)[3]),       \
                   "r"((b)[0]), "r"((b)[1]))
#define MMA_F16(d, a, b)                                                     \
    asm volatile("mma.sync.aligned.m16n8k16.row.col.f16.f16.f16.f16 "      \
                 "{%0,%1}, {%2,%3,%4,%5}, {%6,%7}, {%0,%1};"                 \
                 : "+r"((d)[0]), "+r"((d)[1])                                \
                 : "r"((a)[0]), "r"((a)[1]), "r"((a)[2]), "r"((a)[3]),       \
                   "r"((b)[0]), "r"((b)[1]))

// ---------------- weight prep ----------------------------------------------
__global__ void build_wb_kernel(const float* __restrict__ w) {
    int idx = blockIdx.x * 256 + threadIdx.x;   // 55296 total
    if (idx >= 55296) return;
    int tap = idx >> 11;
    int r = idx & 2047;
    int half = r >> 10;
    int ic = (r >> 6) & 15;
    int oc = (half << 6) | (r & 63);
    g_wb2[idx] = __float2half_rn(w[oc * 432 + ic * 27 + tap]);
}

// ---------------- conv via warp MMA -----------------------------------------
// CTA: 128 positions (2z x 8y x 8x) x 128 oc. 8 warps: Wm=4 x Wn=2.
// A split fp16 (ah + al); B single fp16.
// ah*bh -> f32 acc (half-rate), al*bh -> f16 acc (full-rate), folded at end.
__global__ __launch_bounds__(256, 2)
void conv_mma_kernel(const float* __restrict__ x, const float* __restrict__ cb) {
    extern __shared__ char sm[];
    const u32 smb = smem_u32(sm);
    const int tid = threadIdx.x;
    const int wid = tid >> 5, lane = tid & 31;
    const int n = blockIdx.y, b = n >> 3, i = n & 7;
    const int tile = blockIdx.x;                 // 256 tiles: 4x*4y*16z
    const int x0 = (tile & 3) * 8;
    const int y0 = ((tile >> 2) & 3) * 8;
    const int z0 = (tile >> 4) * 2;

    const int wm = (wid >> 1) * 32;
    const int half = wid & 1;                    // oc half
    const int wn = half * 64;
    const u32 wbase = smb + OFF_B + (u32)wid * (2 * B_BUF);

    // ---- per-warp B staging: 4 x 16B per lane per tap ----
    const int srow0 = lane >> 3, sseg = lane & 7;
    auto stage_tap = [&](int tap, int buf) {
        const __half* gsrc = g_wb2 + ((tap * 2 + half) << 10);
#pragma unroll
        for (int j = 0; j < 4; ++j) {
            int row = srow0 + j * 4;
            u32 d = wbase + (u32)buf * B_BUF + row * B_ROW + sseg * 16;
            const __half* s = gsrc + row * 64 + sseg * 8;
            asm volatile("cp.async.cg.shared.global [%0], [%1], 16;"
                         :: "r"(d), "l"(s));
        }
        asm volatile("cp.async.commit_group;" ::: "memory");
    };

    stage_tap(0, 0);

    // ---- halo tile: [400 rows][ic16] fp16 split, row stride 48B ----
    const float* xn = x + (size_t)n * 524288;
    for (int idx = tid; idx < 6400; idx += 256) {
        int ic = idx / 400, h = idx - ic * 400;
        int hz = h / 100, rp = h - hz * 100;
        int hy = rp / 10, hx = rp - hy * 10;
        int gz = z0 + hz - 1, gy = y0 + hy - 1, gx = x0 + hx - 1;
        float v = 0.0f;
        if ((unsigned)gz < 32u && (unsigned)gy < 32u && (unsigned)gx < 32u)
            v = xn[ic * 32768 + gz * 1024 + gy * 32 + gx];
        __half hh = __float2half_rn(v);
        __half hl = __float2half_rn(v - __half2float(hh));
        int so = h * 48 + ic * 2;
        *(u16*)(sm + OFF_HH + so) = __half_as_ushort(hh);
        *(u16*)(sm + OFF_HL + so) = __half_as_ushort(hl);
    }
    __syncthreads();   // the only CTA barrier before the epilogue

    // ---- per-lane ldmatrix addresses ----
    const int lr = lane & 15;
    const int ksel = (lane >> 4) * 16;
    u32 laddrA[2];
#pragma unroll
    for (int f = 0; f < 2; ++f) {
        int pos = wm + f * 16 + lr;
        int lz = pos >> 6, ly = (pos >> 3) & 7, lx = pos & 7;
        laddrA[f] = smb + OFF_HH + (lz * 100 + ly * 10 + lx) * 48 + ksel;
    }
    u32 baddr[4];
#pragma unroll
    for (int p = 0; p < 4; ++p) {
        int ncloc = p * 16 + ((lane >> 4) & 1) * 8;
        baddr[p] = wbase + (lane & 15) * B_ROW + ncloc * 2;
    }

    float acc[2][8][4];
    u32 accl[2][8][2];   // f16 accumulators for the low term
#pragma unroll
    for (int f = 0; f < 2; ++f)
#pragma unroll
        for (int nf = 0; nf < 8; ++nf) {
#pragma unroll
            for (int q = 0; q < 4; ++q) acc[f][nf][q] = 0.0f;
            accl[f][nf][0] = 0u; accl[f][nf][1] = 0u;
        }

#pragma unroll 1
    for (int tap = 0; tap < 27; ++tap) {
        if (tap + 1 < 27) {
            stage_tap(tap + 1, (tap + 1) & 1);
            asm volatile("cp.async.wait_group 1;" ::: "memory");
        } else {
            asm volatile("cp.async.wait_group 0;" ::: "memory");
        }
        __syncwarp();

        const int dz = tap / 9;
        const int rm = tap - dz * 9;
        const int dy = rm / 3, dx = rm - dy * 3;
        const u32 delta = (u32)((dz * 100 + dy * 10 + dx) * 48);

        u32 ah[2][4], al[2][4];
#pragma unroll
        for (int f = 0; f < 2; ++f) {
            LDSM_X4(ah[f], laddrA[f] + delta);
            LDSM_X4(al[f], laddrA[f] + delta + 19200u);
        }
        const u32 bufo = (u32)((tap & 1) * B_BUF);
#pragma unroll
        for (int p = 0; p < 4; ++p) {
            u32 b0, b1, b2, b3;
            LDSM_X4T(b0, b1, b2, b3, baddr[p] + bufo);
            u32 bb0[2] = {b0, b1}, bb1[2] = {b2, b3};
#pragma unroll
            for (int f = 0; f < 2; ++f) {
                MMA_F32(acc[f][p * 2], ah[f], bb0);
                MMA_F32(acc[f][p * 2 + 1], ah[f], bb1);
                MMA_F16(accl[f][p * 2], al[f], bb0);
                MMA_F16(accl[f][p * 2 + 1], al[f], bb1);
            }
        }
    }

    // ---- epilogue: fold f16 acc, add conv bias, store votes ----
    float2 cbv[8];
#pragma unroll
    for (int nf = 0; nf < 8; ++nf)
        cbv[nf] = *(const float2*)(cb + wn + nf * 8 + (lane & 3) * 2);

#pragma unroll
    for (int f = 0; f < 2; ++f) {
        int pos0 = wm + f * 16 + (lane >> 2);
#pragma unroll
        for (int hrow = 0; hrow < 2; ++hrow) {
            int pos = pos0 + hrow * 8;
            int lz = pos >> 6, ly = (pos >> 3) & 7, lx = pos & 7;
            int gpos = (z0 + lz) * 1024 + (y0 + ly) * 32 + (x0 + lx);
            float* vrow =
                g_votes + (size_t)(b * 32768 + gpos) * 1024 + i * 128;
#pragma unroll
            for (int nf = 0; nf < 8; ++nf) {
                int col = wn + nf * 8 + (lane & 3) * 2;
                __half2 hl = *(__half2*)&accl[f][nf][hrow];
                float2 o;
                o.x = acc[f][nf][hrow * 2 + 0] + __low2float(hl) + cbv[nf].x;
                o.y = acc[f][nf][hrow * 2 + 1] + __high2float(hl) + cbv[nf].y;
                *(float2*)(vrow + col) = o;
            }
        }
    }
}

// ---------------- Routing kernel (fast-math) --------------------------------
__global__ __launch_bounds__(256)
void routing_kernel(const float* __restrict__ biases,
                    float* __restrict__ out) {
    __shared__ float sf[8 * 132];

    const int tid  = threadIdx.x;
    const int wrp  = tid >> 5;
    const int lane = tid & 31;
    const int o = lane >> 2;
    const int g = lane & 3;
    const int blk = blockIdx.x;
    const int b = blk >> 12;
    const int posbase = (blk & 4095) << 3;
    const int pos = posbase + wrp;

    const float4* vp =
        (const float4*)(g_votes + (size_t)(b * 32768 + pos) * 1024);

    float v[8][4];
    float vnsq[8];
#pragma unroll
    for (int in = 0; in < 8; ++in) {
        float4 t = vp[in * 32 + o * 4 + g];
        v[in][0] = t.x; v[in][1] = t.y; v[in][2] = t.z; v[in][3] = t.w;
        float s = t.x * t.x + t.y * t.y + t.z * t.z + t.w * t.w;
        s += __shfl_xor_sync(0xffffffffu, s, 1);
        s += __shfl_xor_sync(0xffffffffu, s, 2);
        vnsq[in] = s;
    }
    const float4 bs = ((const float4*)biases)[o * 4 + g];

    float logit[8];
#pragma unroll
    for (int in = 0; in < 8; ++in) logit[in] = 0.0f;

    float p0, p1, p2, p3;
    for (int it = 0; it < 3; ++it) {
        float route[8];
        if (it == 0) {
#pragma unroll
            for (int in = 0; in < 8; ++in) route[in] = 0.125f;
        } else {
#pragma unroll
            for (int in = 0; in < 8; ++in) {
                float e = __expf(logit[in]);
                float s = e;
                s += __shfl_xor_sync(0xffffffffu, s, 4);
                s += __shfl_xor_sync(0xffffffffu, s, 8);
                s += __shfl_xor_sync(0xffffffffu, s, 16);
                route[in] = __fdividef(e, s);
            }
        }
        p0 = bs.x; p1 = bs.y; p2 = bs.z; p3 = bs.w;
#pragma unroll
        for (int in = 0; in < 8; ++in) {
            p0 = fmaf(route[in], v[in][0], p0);
            p1 = fmaf(route[in], v[in][1], p1);
            p2 = fmaf(route[in], v[in][2], p2);
            p3 = fmaf(route[in], v[in][3], p3);
        }
        if (it < 2) {
            float pnsq = p0 * p0 + p1 * p1 + p2 * p2 + p3 * p3;
            pnsq += __shfl_xor_sync(0xffffffffu, pnsq, 1);
            pnsq += __shfl_xor_sync(0xffffffffu, pnsq, 2);
#pragma unroll
            for (int in = 0; in < 8; ++in) {
                float d = p0 * v[in][0] + p1 * v[in][1] +
                          p2 * v[in][2] + p3 * v[in][3];
                d += __shfl_xor_sync(0xffffffffu, d, 1);
                d += __shfl_xor_sync(0xffffffffu, d, 2);
                // d / max(pn*vn,1e-8) == d * rsqrt(max(pnsq*vnsq,1e-16))
                logit[in] = fmaf(
                    d, rsqrtf(fmaxf(pnsq * vnsq[in], 1e-16f)), logit[in]);
            }
        }
    }

    float nsq = p0 * p0 + p1 * p1 + p2 * p2 + p3 * p3;
    nsq += __shfl_xor_sync(0xffffffffu, nsq, 1);
    nsq += __shfl_xor_sync(0xffffffffu, nsq, 2);
    const float nrm = sqrtf(nsq);
    const float scale = __fdividef(nsq, (1.0f + nsq) * (nrm + 1e-12f));

    ((float4*)sf)[wrp * 33 + (o * 4 + g)] =
        make_float4(p0 * scale, p1 * scale, p2 * scale, p3 * scale);
    __syncthreads();

    for (int j = tid; j < 1024; j += 256) {
        const int oa = j >> 3;
        const int pp = j & 7;
        out[(size_t)(b * 128 + oa) * 32768 + posbase + pp] = sf[pp * 132 + oa];
    }
}

// ---------------- Launch -----------------------------------------------------
extern "C" void kernel_launch(void* const* d_in, const int* in_sizes, int n_in,
                              void* d_out, int out_size) {
    const float* x      = (const float*)d_in[0];
    const float* w      = (const float*)d_in[1];
    const float* cb     = (const float*)d_in[2];
    const float* biases = (const float*)d_in[3];
    float* out = (float*)d_out;

    build_wb_kernel<<<216, 256>>>(w);

    cudaFuncSetAttribute(conv_mma_kernel,
                         cudaFuncAttributeMaxDynamicSharedMemorySize,
                         CONV_SMEM);
    conv_mma_kernel<<<dim3(256, 16), 256, CONV_SMEM>>>(x, cb);
    routing_kernel<<<8192, 256>>>(biases, out);
}

// round 8
// speedup vs baseline: 6.7348x; 1.0265x over previous
#include <cuda_runtime.h>
#include <cuda_fp16.h>
#include <math.h>

typedef unsigned int u32;
typedef unsigned short u16;

// ---------------------------------------------------------------------------
// ConvSlimCapsule3D via warp-level fp16 MMA (2-term split, mixed-rate acc)
// + fast-math routing. Votes stored fp16 (halves DRAM round-trip).
// x(2,8,16,32,32,32) w(128,16,3,3,3) cb(128) biases(8,16,1,1,1)
// ---------------------------------------------------------------------------

__device__ __half g_votesh[67108864];        // [b][pos][i*128+oc], 128 MB
// weights fp16: [tap=27][half=2][ic=16][oc=64]
__device__ __align__(16) __half g_wb2[55296];

// ---- SMEM layout (bytes) ----
#define OFF_HH 0
#define OFF_HL 19200
#define OFF_B  38400
#define B_ROW  144           // 16B-aligned rows; 144%128=16 -> conflict-free
#define B_BUF  (16 * B_ROW)  // 2304
#define CONV_SMEM (38400 + 8 * 2 * B_BUF)   // 75264

__device__ __forceinline__ u32 smem_u32(const void* p) {
    u32 a;
    asm("{ .reg .u64 t; cvta.to.shared.u64 t, %1; cvt.u32.u64 %0, t; }"
        : "=r"(a) : "l"(p));
    return a;
}

#define LDSM_X4(r, a)                                                        \
    asm volatile("ldmatrix.sync.aligned.m8n8.x4.shared.b16 "                 \
                 "{%0,%1,%2,%3}, [%4];"                                      \
                 : "=r"((r)[0]), "=r"((r)[1]), "=r"((r)[2]), "=r"((r)[3])    \
                 : "r"(a))
#define LDSM_X4T(r0, r1, r2, r3, a)                                          \
    asm volatile("ldmatrix.sync.aligned.m8n8.x4.trans.shared.b16 "           \
                 "{%0,%1,%2,%3}, [%4];"                                      \
                 : "=r"(r0), "=r"(r1), "=r"(r2), "=r"(r3) : "r"(a))
#define MMA_F32(d, a, b)                                                     \
    asm volatile("mma.sync.aligned.m16n8k16.row.col.f32.f16.f16.f32 "       \
                 "{%0,%1,%2,%3}, {%4,%5,%6,%7}, {%8,%9}, {%0,%1,%2,%3};"    \
                 : "+f"((d)[0]), "+f"((d)[1]), "+f"((d)[2]), "+f"((d)[3])    \
                 : "r"((a)[0]), "r"((a)[1]), "r"((a)[2]), "r"((a)[3]),       \
                   "r"((b)[0]), "r"((b)[1]))
#define MMA_F16(d, a, b)                                                     \
    asm volatile("mma.sync.aligned.m16n8k16.row.col.f16.f16.f16.f16 "      \
                 "{%0,%1}, {%2,%3,%4,%5}, {%6,%7}, {%0,%1};"                 \
                 : "+r"((d)[0]), "+r"((d)[1])                                \
                 : "r"((a)[0]), "r"((a)[1]), "r"((a)[2]), "r"((a)[3]),       \
                   "r"((b)[0]), "r"((b)[1]))

// ---------------- weight prep ----------------------------------------------
__global__ void build_wb_kernel(const float* __restrict__ w) {
    int idx = blockIdx.x * 256 + threadIdx.x;   // 55296 total
    if (idx >= 55296) return;
    int tap = idx >> 11;
    int r = idx & 2047;
    int half = r >> 10;
    int ic = (r >> 6) & 15;
    int oc = (half << 6) | (r & 63);
    g_wb2[idx] = __float2half_rn(w[oc * 432 + ic * 27 + tap]);
}

// ---------------- conv via warp MMA -----------------------------------------
// CTA: 128 positions (2z x 8y x 8x) x 128 oc. 8 warps: Wm=4 x Wn=2.
// A split fp16 (ah + al); B single fp16.
// ah*bh -> f32 acc (half-rate), al*bh -> f16 acc (full-rate), folded at end.
__global__ __launch_bounds__(256, 2)
void conv_mma_kernel(const float* __restrict__ x, const float* __restrict__ cb) {
    extern __shared__ char sm[];
    const u32 smb = smem_u32(sm);
    const int tid = threadIdx.x;
    const int wid = tid >> 5, lane = tid & 31;
    const int n = blockIdx.y, b = n >> 3, i = n & 7;
    const int tile = blockIdx.x;                 // 256 tiles: 4x*4y*16z
    const int x0 = (tile & 3) * 8;
    const int y0 = ((tile >> 2) & 3) * 8;
    const int z0 = (tile >> 4) * 2;

    const int wm = (wid >> 1) * 32;
    const int half = wid & 1;                    // oc half
    const int wn = half * 64;
    const u32 wbase = smb + OFF_B + (u32)wid * (2 * B_BUF);

    // ---- per-warp B staging: 4 x 16B per lane per tap ----
    const int srow0 = lane >> 3, sseg = lane & 7;
    auto stage_tap = [&](int tap, int buf) {
        const __half* gsrc = g_wb2 + ((tap * 2 + half) << 10);
#pragma unroll
        for (int j = 0; j < 4; ++j) {
            int row = srow0 + j * 4;
            u32 d = wbase + (u32)buf * B_BUF + row * B_ROW + sseg * 16;
            const __half* s = gsrc + row * 64 + sseg * 8;
            asm volatile("cp.async.cg.shared.global [%0], [%1], 16;"
                         :: "r"(d), "l"(s));
        }
        asm volatile("cp.async.commit_group;" ::: "memory");
    };

    stage_tap(0, 0);

    // ---- halo tile: [400 rows][ic16] fp16 split, row stride 48B ----
    const float* xn = x + (size_t)n * 524288;
    for (int idx = tid; idx < 6400; idx += 256) {
        int ic = idx / 400, h = idx - ic * 400;
        int hz = h / 100, rp = h - hz * 100;
        int hy = rp / 10, hx = rp - hy * 10;
        int gz = z0 + hz - 1, gy = y0 + hy - 1, gx = x0 + hx - 1;
        float v = 0.0f;
        if ((unsigned)gz < 32u && (unsigned)gy < 32u && (unsigned)gx < 32u)
            v = xn[ic * 32768 + gz * 1024 + gy * 32 + gx];
        __half hh = __float2half_rn(v);
        __half hl = __float2half_rn(v - __half2float(hh));
        int so = h * 48 + ic * 2;
        *(u16*)(sm + OFF_HH + so) = __half_as_ushort(hh);
        *(u16*)(sm + OFF_HL + so) = __half_as_ushort(hl);
    }
    __syncthreads();   // the only CTA barrier before the epilogue

    // ---- per-lane ldmatrix addresses ----
    const int lr = lane & 15;
    const int ksel = (lane >> 4) * 16;
    u32 laddrA[2];
#pragma unroll
    for (int f = 0; f < 2; ++f) {
        int pos = wm + f * 16 + lr;
        int lz = pos >> 6, ly = (pos >> 3) & 7, lx = pos & 7;
        laddrA[f] = smb + OFF_HH + (lz * 100 + ly * 10 + lx) * 48 + ksel;
    }
    u32 baddr[4];
#pragma unroll
    for (int p = 0; p < 4; ++p) {
        int ncloc = p * 16 + ((lane >> 4) & 1) * 8;
        baddr[p] = wbase + (lane & 15) * B_ROW + ncloc * 2;
    }

    float acc[2][8][4];
    u32 accl[2][8][2];   // f16 accumulators for the low term
#pragma unroll
    for (int f = 0; f < 2; ++f)
#pragma unroll
        for (int nf = 0; nf < 8; ++nf) {
#pragma unroll
            for (int q = 0; q < 4; ++q) acc[f][nf][q] = 0.0f;
            accl[f][nf][0] = 0u; accl[f][nf][1] = 0u;
        }

#pragma unroll 1
    for (int tap = 0; tap < 27; ++tap) {
        if (tap + 1 < 27) {
            stage_tap(tap + 1, (tap + 1) & 1);
            asm volatile("cp.async.wait_group 1;" ::: "memory");
        } else {
            asm volatile("cp.async.wait_group 0;" ::: "memory");
        }
        __syncwarp();

        const int dz = tap / 9;
        const int rm = tap - dz * 9;
        const int dy = rm / 3, dx = rm - dy * 3;
        const u32 delta = (u32)((dz * 100 + dy * 10 + dx) * 48);

        u32 ah[2][4], al[2][4];
#pragma unroll
        for (int f = 0; f < 2; ++f) {
            LDSM_X4(ah[f], laddrA[f] + delta);
            LDSM_X4(al[f], laddrA[f] + delta + 19200u);
        }
        const u32 bufo = (u32)((tap & 1) * B_BUF);
#pragma unroll
        for (int p = 0; p < 4; ++p) {
            u32 b0, b1, b2, b3;
            LDSM_X4T(b0, b1, b2, b3, baddr[p] + bufo);
            u32 bb0[2] = {b0, b1}, bb1[2] = {b2, b3};
#pragma unroll
            for (int f = 0; f < 2; ++f) {
                MMA_F32(acc[f][p * 2], ah[f], bb0);
                MMA_F32(acc[f][p * 2 + 1], ah[f], bb1);
                MMA_F16(accl[f][p * 2], al[f], bb0);
                MMA_F16(accl[f][p * 2 + 1], al[f], bb1);
            }
        }
    }

    // ---- epilogue: fold f16 acc, add conv bias, store fp16 votes ----
    float2 cbv[8];
#pragma unroll
    for (int nf = 0; nf < 8; ++nf)
        cbv[nf] = *(const float2*)(cb + wn + nf * 8 + (lane & 3) * 2);

#pragma unroll
    for (int f = 0; f < 2; ++f) {
        int pos0 = wm + f * 16 + (lane >> 2);
#pragma unroll
        for (int hrow = 0; hrow < 2; ++hrow) {
            int pos = pos0 + hrow * 8;
            int lz = pos >> 6, ly = (pos >> 3) & 7, lx = pos & 7;
            int gpos = (z0 + lz) * 1024 + (y0 + ly) * 32 + (x0 + lx);
            __half* vrow =
                g_votesh + (size_t)(b * 32768 + gpos) * 1024 + i * 128;
#pragma unroll
            for (int nf = 0; nf < 8; ++nf) {
                int col = wn + nf * 8 + (lane & 3) * 2;
                __half2 hl = *(__half2*)&accl[f][nf][hrow];
                float ox = acc[f][nf][hrow * 2 + 0] + __low2float(hl) + cbv[nf].x;
                float oy = acc[f][nf][hrow * 2 + 1] + __high2float(hl) + cbv[nf].y;
                *(__half2*)(vrow + col) = __floats2half2_rn(ox, oy);
            }
        }
    }
}

// ---------------- Routing kernel (fast-math, fp16 vote loads) ---------------
__global__ __launch_bounds__(256)
void routing_kernel(const float* __restrict__ biases,
                    float* __restrict__ out) {
    __shared__ float sf[8 * 132];

    const int tid  = threadIdx.x;
    const int wrp  = tid >> 5;
    const int lane = tid & 31;
    const int o = lane >> 2;
    const int g = lane & 3;
    const int blk = blockIdx.x;
    const int b = blk >> 12;
    const int posbase = (blk & 4095) << 3;
    const int pos = posbase + wrp;

    const uint2* vp =
        (const uint2*)(g_votesh + (size_t)(b * 32768 + pos) * 1024);

    float v[8][4];
    float vnsq[8];
#pragma unroll
    for (int in = 0; in < 8; ++in) {
        uint2 raw = vp[in * 32 + o * 4 + g];
        float2 f01 = __half22float2(*(__half2*)&raw.x);
        float2 f23 = __half22float2(*(__half2*)&raw.y);
        v[in][0] = f01.x; v[in][1] = f01.y;
        v[in][2] = f23.x; v[in][3] = f23.y;
        float s = f01.x * f01.x + f01.y * f01.y +
                  f23.x * f23.x + f23.y * f23.y;
        s += __shfl_xor_sync(0xffffffffu, s, 1);
        s += __shfl_xor_sync(0xffffffffu, s, 2);
        vnsq[in] = s;
    }
    const float4 bs = ((const float4*)biases)[o * 4 + g];

    float logit[8];
#pragma unroll
    for (int in = 0; in < 8; ++in) logit[in] = 0.0f;

    float p0, p1, p2, p3;
    for (int it = 0; it < 3; ++it) {
        float route[8];
        if (it == 0) {
#pragma unroll
            for (int in = 0; in < 8; ++in) route[in] = 0.125f;
        } else {
#pragma unroll
            for (int in = 0; in < 8; ++in) {
                float e = __expf(logit[in]);
                float s = e;
                s += __shfl_xor_sync(0xffffffffu, s, 4);
                s += __shfl_xor_sync(0xffffffffu, s, 8);
                s += __shfl_xor_sync(0xffffffffu, s, 16);
                route[in] = __fdividef(e, s);
            }
        }
        p0 = bs.x; p1 = bs.y; p2 = bs.z; p3 = bs.w;
#pragma unroll
        for (int in = 0; in < 8; ++in) {
            p0 = fmaf(route[in], v[in][0], p0);
            p1 = fmaf(route[in], v[in][1], p1);
            p2 = fmaf(route[in], v[in][2], p2);
            p3 = fmaf(route[in], v[in][3], p3);
        }
        if (it < 2) {
            float pnsq = p0 * p0 + p1 * p1 + p2 * p2 + p3 * p3;
            pnsq += __shfl_xor_sync(0xffffffffu, pnsq, 1);
            pnsq += __shfl_xor_sync(0xffffffffu, pnsq, 2);
#pragma unroll
            for (int in = 0; in < 8; ++in) {
                float d = p0 * v[in][0] + p1 * v[in][1] +
                          p2 * v[in][2] + p3 * v[in][3];
                d += __shfl_xor_sync(0xffffffffu, d, 1);
                d += __shfl_xor_sync(0xffffffffu, d, 2);
                logit[in] = fmaf(
                    d, rsqrtf(fmaxf(pnsq * vnsq[in], 1e-16f)), logit[in]);
            }
        }
    }

    float nsq = p0 * p0 + p1 * p1 + p2 * p2 + p3 * p3;
    nsq += __shfl_xor_sync(0xffffffffu, nsq, 1);
    nsq += __shfl_xor_sync(0xffffffffu, nsq, 2);
    const float nrm = sqrtf(nsq);
    const float scale = __fdividef(nsq, (1.0f + nsq) * (nrm + 1e-12f));

    ((float4*)sf)[wrp * 33 + (o * 4 + g)] =
        make_float4(p0 * scale, p1 * scale, p2 * scale, p3 * scale);
    __syncthreads();

    for (int j = tid; j < 1024; j += 256) {
        const int oa = j >> 3;
        const int pp = j & 7;
        out[(size_t)(b * 128 + oa) * 32768 + posbase + pp] = sf[pp * 132 + oa];
    }
}

// ---------------- Launch -----------------------------------------------------
extern "C" void kernel_launch(void* const* d_in, const int* in_sizes, int n_in,
                              void* d_out, int out_size) {
    const float* x      = (const float*)d_in[0];
    const float* w      = (const float*)d_in[1];
    const float* cb     = (const float*)d_in[2];
    const float* biases = (const float*)d_in[3];
    float* out = (float*)d_out;

    build_wb_kernel<<<216, 256>>>(w);

    cudaFuncSetAttribute(conv_mma_kernel,
                         cudaFuncAttributeMaxDynamicSharedMemorySize,
                         CONV_SMEM);
    conv_mma_kernel<<<dim3(256, 16), 256, CONV_SMEM>>>(x, cb);
    routing_kernel<<<8192, 256>>>(biases, out);
}